// round 15
// baseline (speedup 1.0000x reference)
#include <cuda_runtime.h>
#include <math.h>
#include <stdint.h>

#define B_   4
#define N_   8192
#define DIM_ 512
#define H_   8
#define DH_  64
#define BH_  (B_*H_)          // 32
#define MROWS (B_*N_)         // 32768
#define QKVN  (3*DIM_)        // 1536

typedef unsigned long long u64;

// ---------------- scratch (device globals; no allocs allowed) ----------------
__device__ float g_ctx[BH_*DH_*DH_];   // [bh][d][e]  UNNORMALIZED (divide in w2)
__device__ float g_w2[(size_t)B_*DIM_*DIM_];   // [b][h*64+d][c] = (ctx_h/ksum) @ Wout_h
__device__ float g_w3[(size_t)B_*DIM_*DIM_];   // [b][k][c]      = Wv @ W2[b]
__device__ float g_ksum[BH_*DH_];      // [bh][e] = sum_n exp(k)
__device__ int   g_maskflags[2];

// ---------------- helpers ----------------
__device__ __forceinline__ uint32_t smem_u32(const void* p) {
    uint32_t a;
    asm("{ .reg .u64 t; cvta.to.shared.u64 t, %1; cvt.u32.u64 %0, t; }" : "=r"(a) : "l"(p));
    return a;
}
__device__ __forceinline__ void cp16(uint32_t dst, const void* src) {
    asm volatile("cp.async.ca.shared.global [%0], [%1], 16;" :: "r"(dst), "l"(src));
}
__device__ __forceinline__ void cp_commit() {
    asm volatile("cp.async.commit_group;" ::: "memory");
}
template<int N> __device__ __forceinline__ void cp_wait() {
    asm volatile("cp.async.wait_group %0;" :: "n"(N) : "memory");
}

// packed f32x2 helpers (FFMA2)
__device__ __forceinline__ u64 pack_dup(float a) {
    u64 p;
    asm("mov.b64 %0, {%1, %1};" : "=l"(p) : "f"(a));
    return p;
}
__device__ __forceinline__ void fma2(u64& d, u64 a, u64 b) {
    asm("fma.rn.f32x2 %0, %1, %2, %0;" : "+l"(d) : "l"(a), "l"(b));
}
__device__ __forceinline__ void unpack2(float& lo, float& hi, u64 p) {
    asm("mov.b64 {%0, %1}, %2;" : "=f"(lo), "=f"(hi) : "l"(p));
}

// smem geometry: A stage = 128 rows x (16 floats + 4 pad) = 10240 B
//                B stage = 16 rows x (128 floats + 4 pad) = 8448 B
#define A_STAGE 10240
#define B_BASE  20480
#define B_STAGE 8448
#define SMEM_TOT 37376

// =============================================================================
// Shared cp.async double-buffered f32x2 mainloop (generic B stride), 256 thr.
// =============================================================================
__device__ __forceinline__ void gemm_mainloop(u64 (&accp)[8][4], char* sm, uint32_t sb,
                                              const float* __restrict__ Ag, int AW,
                                              const float* __restrict__ Bg, int BW,
                                              int ch0, int nch) {
    const int tid = threadIdx.x;
    const int ty = tid >> 4, tx = tid & 15;
    const int m0 = ty * 8;

    #pragma unroll
    for (int i = 0; i < 8; ++i)
        #pragma unroll
        for (int j = 0; j < 4; ++j) accp[i][j] = 0ull;

    const int ar_ = tid >> 2,  ac_ = tid & 3;
    const int br_ = tid >> 5,  bc_ = tid & 31;

    auto issue = [&](int ch, int p) {
        uint32_t Ab = sb + p * A_STAGE;
        uint32_t Bb = sb + B_BASE + p * B_STAGE;
        int kc = (ch0 + ch) * 16;
        #pragma unroll
        for (int i = 0; i < 2; ++i) {
            int r = ar_ + i * 64;
            cp16(Ab + r * 80 + ac_ * 16, Ag + (size_t)r * AW + kc + ac_ * 4);
        }
        #pragma unroll
        for (int i = 0; i < 2; ++i) {
            int r = br_ + i * 8;
            cp16(Bb + r * 528 + bc_ * 16, Bg + (size_t)(kc + r) * BW + bc_ * 4);
        }
    };

    issue(0, 0);
    cp_commit();

    #pragma unroll 1
    for (int ch = 0; ch < nch; ++ch) {
        int p = ch & 1;
        cp_wait<0>();
        __syncthreads();
        if (ch < nch - 1) { issue(ch + 1, p ^ 1); cp_commit(); }

        const float* As = (const float*)(sm + p * A_STAGE);
        const char*  Bs = sm + B_BASE + p * B_STAGE;

        #pragma unroll
        for (int kk = 0; kk < 16; ++kk) {
            const char* brow = Bs + kk * 528 + tx * 32;
            u64 b0 = *(const u64*)(brow);
            u64 b1 = *(const u64*)(brow + 8);
            u64 b2 = *(const u64*)(brow + 16);
            u64 b3 = *(const u64*)(brow + 24);
            #pragma unroll
            for (int i = 0; i < 8; ++i) {
                u64 pa = pack_dup(As[(m0 + i) * 20 + kk]);
                fma2(accp[i][0], pa, b0);
                fma2(accp[i][1], pa, b1);
                fma2(accp[i][2], pa, b2);
                fma2(accp[i][3], pa, b3);
            }
        }
    }
}

// =============================================================================
// GEMM1 FUSED: per (b,h) CTA computes [q_h | k_h] = X_band @ W_gather, then
// q-softmax / k exp+mask / ksum / partial ctx — no q/k gmem round trip.
// grid (32 bh, 64 nbands of 128 rows).
// =============================================================================
__global__ __launch_bounds__(256, 2) void gemm1_fused(const float* __restrict__ X,
                                                      const float* __restrict__ W,
                                                      const void* __restrict__ mask) {
    __shared__ __align__(16) char sm[SMEM_TOT];
    uint32_t sb = smem_u32(sm);

    const int bh = blockIdx.x, nband = blockIdx.y;
    const int b = bh >> 3, h = bh & 7;
    const float* Ag = X + ((size_t)b * N_ + nband * 128) * DIM_;

    const int tid = threadIdx.x;
    const int ty = tid >> 4, tx = tid & 15;
    const int m0 = ty * 8;

    u64 accp[8][4];
    #pragma unroll
    for (int i = 0; i < 8; ++i)
        #pragma unroll
        for (int j = 0; j < 4; ++j) accp[i][j] = 0ull;

    const int ar_ = tid >> 2,  ac_ = tid & 3;
    const int br_ = tid >> 5,  bc_ = tid & 31;
    const int bcol = (bc_ < 16) ? (h * 64 + bc_ * 4)
                                : (512 + h * 64 + (bc_ - 16) * 4);

    auto issue = [&](int ch, int p) {
        uint32_t Ab = sb + p * A_STAGE;
        uint32_t Bb = sb + B_BASE + p * B_STAGE;
        int kc = ch * 16;
        #pragma unroll
        for (int i = 0; i < 2; ++i) {
            int r = ar_ + i * 64;
            cp16(Ab + r * 80 + ac_ * 16, Ag + (size_t)r * DIM_ + kc + ac_ * 4);
        }
        #pragma unroll
        for (int i = 0; i < 2; ++i) {
            int r = br_ + i * 8;
            cp16(Bb + r * 528 + bc_ * 16, W + (size_t)(kc + r) * QKVN + bcol);
        }
    };

    issue(0, 0);
    cp_commit();

    #pragma unroll 1
    for (int ch = 0; ch < 32; ++ch) {
        int p = ch & 1;
        cp_wait<0>();
        __syncthreads();
        if (ch < 31) { issue(ch + 1, p ^ 1); cp_commit(); }

        const float* As = (const float*)(sm + p * A_STAGE);
        const char*  Bs = sm + B_BASE + p * B_STAGE;

        #pragma unroll
        for (int kk = 0; kk < 16; ++kk) {
            const char* brow = Bs + kk * 528 + tx * 32;
            u64 b0 = *(const u64*)(brow);
            u64 b1 = *(const u64*)(brow + 8);
            u64 b2 = *(const u64*)(brow + 16);
            u64 b3 = *(const u64*)(brow + 24);
            #pragma unroll
            for (int i = 0; i < 8; ++i) {
                u64 pa = pack_dup(As[(m0 + i) * 20 + kk]);
                fma2(accp[i][0], pa, b0);
                fma2(accp[i][1], pa, b1);
                fma2(accp[i][2], pa, b2);
                fma2(accp[i][3], pa, b3);
            }
        }
    }

    float acc[8][8];
    #pragma unroll
    for (int i = 0; i < 8; ++i)
        #pragma unroll
        for (int j = 0; j < 4; ++j)
            unpack2(acc[i][2*j], acc[i][2*j+1], accp[i][j]);

    // ---- epilogue: q softmax (tx<8) / k exp+mask (tx>=8) ----
    const float SCALE = 0.125f;
    const int f32f = g_maskflags[0], u8f = g_maskflags[1];

    bool mzv[8];
    if (tx >= 8) {
        #pragma unroll
        for (int i = 0; i < 8; ++i) {
            int grow = bh * N_ + nband * 128 + ty * 8 + i;
            if (f32f)      mzv[i] = ((const float*)mask)[grow] != 0.f;
            else if (u8f)  mzv[i] = ((const unsigned char*)mask)[grow] != 0;
            else           mzv[i] = ((const int*)mask)[grow] != 0;
        }
    }

    float ksl[8];
    #pragma unroll
    for (int j = 0; j < 8; ++j) ksl[j] = 0.f;

    #pragma unroll
    for (int i = 0; i < 8; ++i) {
        float sc[8];
        float lsum = 0.f;
        #pragma unroll
        for (int j = 0; j < 8; ++j) { sc[j] = __expf(acc[i][j] * SCALE); lsum += sc[j]; }
        #pragma unroll
        for (int off = 4; off > 0; off >>= 1)
            lsum += __shfl_xor_sync(0xffffffff, lsum, off);
        float inv = 1.f / lsum;

        if (tx < 8) {
            #pragma unroll
            for (int j = 0; j < 8; ++j) acc[i][j] = sc[j] * inv;
        } else {
            bool mz = mzv[i];
            #pragma unroll
            for (int j = 0; j < 8; ++j) {
                float ez = __expf(acc[i][j]);
                ksl[j] += ez;                    // ksum pre-mask
                acc[i][j] = mz ? 0.f : ez;
            }
        }
    }

    // ---- ksum reduction (red at sm+32768, 4KB) ----
    float* red = (float*)(sm + 32768);
    __syncthreads();                 // mainloop smem free
    if (tx >= 8) {
        #pragma unroll
        for (int j = 0; j < 8; ++j) red[ty * 64 + (tx - 8) * 8 + j] = ksl[j];
    }
    __syncthreads();
    if (tid < 64) {
        float s = 0.f;
        #pragma unroll
        for (int r = 0; r < 16; ++r) s += red[r * 64 + tid];
        atomicAdd(&g_ksum[bh * 64 + tid], s);
    }

    // ---- partial ctx: two 64-row halves staged in smem ----
    float* qsm = (float*)sm;             // [64][64]
    float* ksm = (float*)(sm + 16384);   // [64][64]
    const int d0 = (tid >> 4) * 4, e0 = (tid & 15) * 4;

    u64 cacc[4][2];
    #pragma unroll
    for (int i = 0; i < 4; ++i) { cacc[i][0] = 0ull; cacc[i][1] = 0ull; }

    #pragma unroll
    for (int half = 0; half < 2; ++half) {
        __syncthreads();
        if ((ty >> 3) == half) {
            int lty = ty & 7;
            if (tx < 8) {
                #pragma unroll
                for (int i = 0; i < 8; ++i)
                    #pragma unroll
                    for (int j = 0; j < 8; ++j)
                        qsm[(lty * 8 + i) * 64 + tx * 8 + j] = acc[i][j];
            } else {
                #pragma unroll
                for (int i = 0; i < 8; ++i)
                    #pragma unroll
                    for (int j = 0; j < 8; ++j)
                        ksm[(lty * 8 + i) * 64 + (tx - 8) * 8 + j] = acc[i][j];
            }
        }
        __syncthreads();

        #pragma unroll 4
        for (int r = 0; r < 64; ++r) {
            float4 qa = *(const float4*)&qsm[r * 64 + d0];
            u64 kb0 = *(const u64*)&ksm[r * 64 + e0];
            u64 kb1 = *(const u64*)&ksm[r * 64 + e0 + 2];
            u64 p0 = pack_dup(qa.x), p1 = pack_dup(qa.y);
            u64 p2 = pack_dup(qa.z), p3 = pack_dup(qa.w);
            fma2(cacc[0][0], p0, kb0); fma2(cacc[0][1], p0, kb1);
            fma2(cacc[1][0], p1, kb0); fma2(cacc[1][1], p1, kb1);
            fma2(cacc[2][0], p2, kb0); fma2(cacc[2][1], p2, kb1);
            fma2(cacc[3][0], p3, kb0); fma2(cacc[3][1], p3, kb1);
        }
    }

    #pragma unroll
    for (int i = 0; i < 4; ++i) {
        float v0, v1, v2, v3;
        unpack2(v0, v1, cacc[i][0]);
        unpack2(v2, v3, cacc[i][1]);
        float* dst = &g_ctx[bh * 4096 + (d0 + i) * 64 + e0];
        atomicAdd(dst + 0, v0);
        atomicAdd(dst + 1, v1);
        atomicAdd(dst + 2, v2);
        atomicAdd(dst + 3, v3);
    }
}

// =============================================================================
// W3[b] += Wv_slice @ W2[b]  (K-split 2, atomicAdd). grid (4, 16, 2), 512 thr:
// 16 warps/CTA -> 4 warps/SMSP saturates FFMA2 from one resident CTA.
// Thread map 32x16: 4 m-rows x 8 n-cols each.
// =============================================================================
__global__ __launch_bounds__(512, 1) void w3_kernel(const float* __restrict__ Wqkv) {
    __shared__ __align__(16) char sm[SMEM_TOT];
    uint32_t sb = smem_u32(sm);

    const int nBase = blockIdx.x * 128;
    const int mBase = blockIdx.y * 128;
    const int b     = mBase >> 9;
    const int kr0   = mBase & 511;
    const int ks    = blockIdx.z;                // 0..1

    const float* Ag = Wqkv + (size_t)kr0 * QKVN + 1024;
    const float* Bg = g_w2 + (size_t)b * DIM_ * DIM_ + nBase;

    const int tid = threadIdx.x;
    const int ty = tid >> 4, tx = tid & 15;      // ty 0..31, tx 0..15
    const int m0 = ty * 4;

    u64 accp[4][4];
    #pragma unroll
    for (int i = 0; i < 4; ++i)
        #pragma unroll
        for (int j = 0; j < 4; ++j) accp[i][j] = 0ull;

    const int ar_ = tid >> 2,  ac_ = tid & 3;    // 128 rows x 4 float4
    const int br_ = tid >> 5,  bc_ = tid & 31;   // 16 rows x 32 float4

    auto issue = [&](int ch, int p) {
        uint32_t Ab = sb + p * A_STAGE;
        uint32_t Bb = sb + B_BASE + p * B_STAGE;
        int kc = (ks * 16 + ch) * 16;
        cp16(Ab + ar_ * 80 + ac_ * 16, Ag + (size_t)ar_ * QKVN + kc + ac_ * 4);
        cp16(Bb + br_ * 528 + bc_ * 16, Bg + (size_t)(kc + br_) * DIM_ + bc_ * 4);
    };

    issue(0, 0);
    cp_commit();

    #pragma unroll 1
    for (int ch = 0; ch < 16; ++ch) {
        int p = ch & 1;
        cp_wait<0>();
        __syncthreads();
        if (ch < 15) { issue(ch + 1, p ^ 1); cp_commit(); }

        const float* As = (const float*)(sm + p * A_STAGE);
        const char*  Bs = sm + B_BASE + p * B_STAGE;

        #pragma unroll
        for (int kk = 0; kk < 16; ++kk) {
            const char* brow = Bs + kk * 528 + tx * 32;
            u64 b0 = *(const u64*)(brow);
            u64 b1 = *(const u64*)(brow + 8);
            u64 b2 = *(const u64*)(brow + 16);
            u64 b3 = *(const u64*)(brow + 24);
            #pragma unroll
            for (int i = 0; i < 4; ++i) {
                u64 pa = pack_dup(As[(m0 + i) * 20 + kk]);
                fma2(accp[i][0], pa, b0);
                fma2(accp[i][1], pa, b1);
                fma2(accp[i][2], pa, b2);
                fma2(accp[i][3], pa, b3);
            }
        }
    }

    const int n0 = tx * 8;
    #pragma unroll
    for (int i = 0; i < 4; ++i) {
        float v[8];
        #pragma unroll
        for (int j = 0; j < 4; ++j) unpack2(v[2*j], v[2*j+1], accp[i][j]);
        float* dst = g_w3 + (size_t)b * DIM_ * DIM_ + (size_t)(kr0 + m0 + i) * DIM_ + nBase + n0;
        #pragma unroll
        for (int j = 0; j < 8; ++j) atomicAdd(dst + j, v[j]);
    }
}

// =============================================================================
// GEMM2: out = X @ W3[b] + bout.  grid (4, 256).
// =============================================================================
__global__ __launch_bounds__(256, 2) void gemm2_cp(const float* __restrict__ X,
                                                   const float* __restrict__ bias,
                                                   float* __restrict__ out) {
    __shared__ __align__(16) char sm[SMEM_TOT];
    uint32_t sb = smem_u32(sm);

    const int nBase = blockIdx.x * 128;
    const int mBase = blockIdx.y * 128;
    const int b     = mBase >> 13;

    u64 accp[8][4];
    gemm_mainloop(accp, sm, sb,
                  X + (size_t)mBase * DIM_, DIM_,
                  g_w3 + (size_t)b * DIM_ * DIM_ + nBase, DIM_, 0, 32);

    float acc[8][8];
    #pragma unroll
    for (int i = 0; i < 8; ++i)
        #pragma unroll
        for (int j = 0; j < 4; ++j)
            unpack2(acc[i][2*j], acc[i][2*j+1], accp[i][j]);

    const int tid = threadIdx.x;
    const int ty = tid >> 4, tx = tid & 15;
    const int m0 = ty * 8, n0 = tx * 8;

    #pragma unroll
    for (int i = 0; i < 8; ++i) {
        int gm = mBase + m0 + i;
        #pragma unroll
        for (int j = 0; j < 8; j += 4) {
            int gn = nBase + n0 + j;
            float4 bv = *(const float4*)&bias[gn];
            float4 o = make_float4(acc[i][j] + bv.x, acc[i][j+1] + bv.y,
                                   acc[i][j+2] + bv.z, acc[i][j+3] + bv.w);
            *(float4*)&out[(size_t)gm * DIM_ + gn] = o;
        }
    }
}

// =============================================================================
// Mask dtype detection (bool may be serialized as u8 / i32 / f32).
// =============================================================================
__global__ __launch_bounds__(256) void detect_mask_kernel(const unsigned char* __restrict__ m) {
    int i = blockIdx.x * 256 + threadIdx.x;
    uchar4 v = ((const uchar4*)m)[i];
    bool f32sig = (v.w == 0x3f);
    bool offnz  = (v.y | v.z | v.w) != 0;
    unsigned b1 = __ballot_sync(0xffffffff, f32sig);
    unsigned b2 = __ballot_sync(0xffffffff, offnz);
    if ((threadIdx.x & 31) == 0) {
        if (b1) atomicOr(&g_maskflags[0], 1);
        if (b2) atomicOr(&g_maskflags[1], 1);
    }
}

// =============================================================================
// W2[b][h*64+d][c] = sum_e (ctxU[bh][d][e]/ksum[bh][e]) * Wout[h*64+e][c]
// grid (32 bh, 4 c-blocks of 128). Wout staged in smem (two 32-row halves).
// =============================================================================
__global__ __launch_bounds__(256) void w2_kernel(const float* __restrict__ Wout) {
    int bh = blockIdx.x, cb = blockIdx.y;
    int b = bh >> 3, h = bh & 7;
    __shared__ float cs[64][64];
    __shared__ float ws[32][128];
    int t = threadIdx.x;

    float4 kv = *(const float4*)&g_ksum[bh * 64 + (t & 15) * 4];
    const float4* cp4 = (const float4*)(g_ctx + bh * 4096);
    #pragma unroll
    for (int u = 0; u < 4; ++u) {
        float4 c4 = cp4[u * 256 + t];
        c4.x /= kv.x; c4.y /= kv.y; c4.z /= kv.z; c4.w /= kv.w;
        ((float4*)cs)[u * 256 + t] = c4;
    }

    int ty = t >> 4, tx = t & 15;
    int c0 = cb * 128 + tx * 8;
    const float* wbase = Wout + (size_t)(h * 64) * DIM_ + cb * 128;

    float acc[4][8];
    #pragma unroll
    for (int i = 0; i < 4; ++i)
        #pragma unroll
        for (int j = 0; j < 8; ++j) acc[i][j] = 0.f;

    #pragma unroll
    for (int half = 0; half < 2; ++half) {
        if (half) __syncthreads();
        #pragma unroll
        for (int u = 0; u < 4; ++u) {
            int idx = u * 256 + t;
            int e = idx >> 5, c4 = idx & 31;
            *(float4*)&ws[e][c4 * 4] =
                *(const float4*)&wbase[(size_t)(half * 32 + e) * DIM_ + c4 * 4];
        }
        __syncthreads();

        #pragma unroll 4
        for (int e = 0; e < 32; ++e) {
            float4 w0 = *(const float4*)&ws[e][tx * 8];
            float4 w1 = *(const float4*)&ws[e][tx * 8 + 4];
            float wv[8] = {w0.x, w0.y, w0.z, w0.w, w1.x, w1.y, w1.z, w1.w};
            #pragma unroll
            for (int i = 0; i < 4; ++i) {
                float cv = cs[ty * 4 + i][half * 32 + e];
                #pragma unroll
                for (int j = 0; j < 8; ++j) acc[i][j] += cv * wv[j];
            }
        }
    }

    #pragma unroll
    for (int i = 0; i < 4; ++i) {
        size_t row = (size_t)b * DIM_ + h * 64 + ty * 4 + i;
        float* dst = g_w2 + row * DIM_ + c0;
        *(float4*)(dst)     = make_float4(acc[i][0], acc[i][1], acc[i][2], acc[i][3]);
        *(float4*)(dst + 4) = make_float4(acc[i][4], acc[i][5], acc[i][6], acc[i][7]);
    }
}

// =============================================================================
extern "C" void kernel_launch(void* const* d_in, const int* in_sizes, int n_in,
                              void* d_out, int out_size) {
    const float* x    = (const float*)d_in[0];
    const void*  mask = d_in[1];
    const float* Wqkv = (const float*)d_in[2];
    const float* Wout = (const float*)d_in[3];
    const float* bout = (const float*)d_in[4];
    float* out = (float*)d_out;

    void *pks, *pctx, *pfl, *pw3;
    cudaGetSymbolAddress(&pks,  g_ksum);
    cudaGetSymbolAddress(&pctx, g_ctx);
    cudaGetSymbolAddress(&pfl,  g_maskflags);
    cudaGetSymbolAddress(&pw3,  g_w3);
    cudaMemsetAsync(pks,  0, sizeof(float) * BH_ * DH_);
    cudaMemsetAsync(pctx, 0, sizeof(float) * BH_ * DH_ * DH_);
    cudaMemsetAsync(pfl,  0, 2 * sizeof(int));
    cudaMemsetAsync(pw3,  0, sizeof(float) * B_ * DIM_ * DIM_);

    detect_mask_kernel<<<(BH_ * N_) / 1024, 256>>>((const unsigned char*)mask);

    gemm1_fused<<<dim3(BH_, N_ / 128), 256>>>(x, Wqkv, mask);   // q,k + ctx + ksum

    w2_kernel<<<dim3(BH_, 4), 256>>>(Wout);
    w3_kernel<<<dim3(4, 16, 2), 512>>>(Wqkv);

    gemm2_cp<<<dim3(DIM_ / 128, MROWS / 128), 256>>>(x, bout, out);
}

// round 16
// speedup vs baseline: 1.0167x; 1.0167x over previous
#include <cuda_runtime.h>
#include <math.h>
#include <stdint.h>

#define B_   4
#define N_   8192
#define DIM_ 512
#define H_   8
#define DH_  64
#define BH_  (B_*H_)          // 32
#define MROWS (B_*N_)         // 32768
#define QKVN  (3*DIM_)        // 1536

typedef unsigned long long u64;

// ---------------- scratch (device globals; no allocs allowed) ----------------
__device__ float g_ctx[BH_*DH_*DH_];   // [bh][d][e]  UNNORMALIZED (divide in w2)
__device__ float g_w2[(size_t)B_*DIM_*DIM_];   // [b][h*64+d][c] = (ctx_h/ksum) @ Wout_h
__device__ float g_w3[(size_t)B_*DIM_*DIM_];   // [b][k][c]      = Wv @ W2[b]
__device__ float g_ksum[BH_*DH_];      // [bh][e] = sum_n exp(k)
__device__ int   g_maskflags[2];

// ---------------- helpers ----------------
__device__ __forceinline__ uint32_t smem_u32(const void* p) {
    uint32_t a;
    asm("{ .reg .u64 t; cvta.to.shared.u64 t, %1; cvt.u32.u64 %0, t; }" : "=r"(a) : "l"(p));
    return a;
}
__device__ __forceinline__ void cp16(uint32_t dst, const void* src) {
    asm volatile("cp.async.ca.shared.global [%0], [%1], 16;" :: "r"(dst), "l"(src));
}
__device__ __forceinline__ void cp_commit() {
    asm volatile("cp.async.commit_group;" ::: "memory");
}
template<int N> __device__ __forceinline__ void cp_wait() {
    asm volatile("cp.async.wait_group %0;" :: "n"(N) : "memory");
}

// packed f32x2 helpers (FFMA2)
__device__ __forceinline__ u64 pack_dup(float a) {
    u64 p;
    asm("mov.b64 %0, {%1, %1};" : "=l"(p) : "f"(a));
    return p;
}
__device__ __forceinline__ void fma2(u64& d, u64 a, u64 b) {
    asm("fma.rn.f32x2 %0, %1, %2, %0;" : "+l"(d) : "l"(a), "l"(b));
}
__device__ __forceinline__ void unpack2(float& lo, float& hi, u64 p) {
    asm("mov.b64 {%0, %1}, %2;" : "=f"(lo), "=f"(hi) : "l"(p));
}

// smem geometry: A stage = 128 rows x (16 floats + 4 pad) = 10240 B
//                B stage = 16 rows x (128 floats + 4 pad) = 8448 B
#define A_STAGE 10240
#define B_BASE  20480
#define B_STAGE 8448
#define SMEM_TOT 37376

// =============================================================================
// Shared cp.async double-buffered f32x2 mainloop (generic B stride), 256 thr.
// =============================================================================
__device__ __forceinline__ void gemm_mainloop(u64 (&accp)[8][4], char* sm, uint32_t sb,
                                              const float* __restrict__ Ag, int AW,
                                              const float* __restrict__ Bg, int BW,
                                              int ch0, int nch) {
    const int tid = threadIdx.x;
    const int ty = tid >> 4, tx = tid & 15;
    const int m0 = ty * 8;

    #pragma unroll
    for (int i = 0; i < 8; ++i)
        #pragma unroll
        for (int j = 0; j < 4; ++j) accp[i][j] = 0ull;

    const int ar_ = tid >> 2,  ac_ = tid & 3;
    const int br_ = tid >> 5,  bc_ = tid & 31;

    auto issue = [&](int ch, int p) {
        uint32_t Ab = sb + p * A_STAGE;
        uint32_t Bb = sb + B_BASE + p * B_STAGE;
        int kc = (ch0 + ch) * 16;
        #pragma unroll
        for (int i = 0; i < 2; ++i) {
            int r = ar_ + i * 64;
            cp16(Ab + r * 80 + ac_ * 16, Ag + (size_t)r * AW + kc + ac_ * 4);
        }
        #pragma unroll
        for (int i = 0; i < 2; ++i) {
            int r = br_ + i * 8;
            cp16(Bb + r * 528 + bc_ * 16, Bg + (size_t)(kc + r) * BW + bc_ * 4);
        }
    };

    issue(0, 0);
    cp_commit();

    #pragma unroll 1
    for (int ch = 0; ch < nch; ++ch) {
        int p = ch & 1;
        cp_wait<0>();
        __syncthreads();
        if (ch < nch - 1) { issue(ch + 1, p ^ 1); cp_commit(); }

        const float* As = (const float*)(sm + p * A_STAGE);
        const char*  Bs = sm + B_BASE + p * B_STAGE;

        #pragma unroll
        for (int kk = 0; kk < 16; ++kk) {
            const char* brow = Bs + kk * 528 + tx * 32;
            u64 b0 = *(const u64*)(brow);
            u64 b1 = *(const u64*)(brow + 8);
            u64 b2 = *(const u64*)(brow + 16);
            u64 b3 = *(const u64*)(brow + 24);
            #pragma unroll
            for (int i = 0; i < 8; ++i) {
                u64 pa = pack_dup(As[(m0 + i) * 20 + kk]);
                fma2(accp[i][0], pa, b0);
                fma2(accp[i][1], pa, b1);
                fma2(accp[i][2], pa, b2);
                fma2(accp[i][3], pa, b3);
            }
        }
    }
}

// =============================================================================
// GEMM1 FUSED: per (b,h) CTA computes [q_h | k_h] = X_band @ W_gather, then
// q-softmax / k exp+mask / ksum / partial ctx — no q/k gmem round trip.
// grid (32 bh, 64 nbands of 128 rows).
// =============================================================================
__global__ __launch_bounds__(256, 2) void gemm1_fused(const float* __restrict__ X,
                                                      const float* __restrict__ W,
                                                      const void* __restrict__ mask) {
    __shared__ __align__(16) char sm[SMEM_TOT];
    uint32_t sb = smem_u32(sm);

    const int bh = blockIdx.x, nband = blockIdx.y;
    const int b = bh >> 3, h = bh & 7;
    const float* Ag = X + ((size_t)b * N_ + nband * 128) * DIM_;

    const int tid = threadIdx.x;
    const int ty = tid >> 4, tx = tid & 15;
    const int m0 = ty * 8;

    u64 accp[8][4];
    #pragma unroll
    for (int i = 0; i < 8; ++i)
        #pragma unroll
        for (int j = 0; j < 4; ++j) accp[i][j] = 0ull;

    const int ar_ = tid >> 2,  ac_ = tid & 3;
    const int br_ = tid >> 5,  bc_ = tid & 31;
    const int bcol = (bc_ < 16) ? (h * 64 + bc_ * 4)
                                : (512 + h * 64 + (bc_ - 16) * 4);

    auto issue = [&](int ch, int p) {
        uint32_t Ab = sb + p * A_STAGE;
        uint32_t Bb = sb + B_BASE + p * B_STAGE;
        int kc = ch * 16;
        #pragma unroll
        for (int i = 0; i < 2; ++i) {
            int r = ar_ + i * 64;
            cp16(Ab + r * 80 + ac_ * 16, Ag + (size_t)r * DIM_ + kc + ac_ * 4);
        }
        #pragma unroll
        for (int i = 0; i < 2; ++i) {
            int r = br_ + i * 8;
            cp16(Bb + r * 528 + bc_ * 16, W + (size_t)(kc + r) * QKVN + bcol);
        }
    };

    issue(0, 0);
    cp_commit();

    #pragma unroll 1
    for (int ch = 0; ch < 32; ++ch) {
        int p = ch & 1;
        cp_wait<0>();
        __syncthreads();
        if (ch < 31) { issue(ch + 1, p ^ 1); cp_commit(); }

        const float* As = (const float*)(sm + p * A_STAGE);
        const char*  Bs = sm + B_BASE + p * B_STAGE;

        #pragma unroll
        for (int kk = 0; kk < 16; ++kk) {
            const char* brow = Bs + kk * 528 + tx * 32;
            u64 b0 = *(const u64*)(brow);
            u64 b1 = *(const u64*)(brow + 8);
            u64 b2 = *(const u64*)(brow + 16);
            u64 b3 = *(const u64*)(brow + 24);
            #pragma unroll
            for (int i = 0; i < 8; ++i) {
                u64 pa = pack_dup(As[(m0 + i) * 20 + kk]);
                fma2(accp[i][0], pa, b0);
                fma2(accp[i][1], pa, b1);
                fma2(accp[i][2], pa, b2);
                fma2(accp[i][3], pa, b3);
            }
        }
    }

    float acc[8][8];
    #pragma unroll
    for (int i = 0; i < 8; ++i)
        #pragma unroll
        for (int j = 0; j < 4; ++j)
            unpack2(acc[i][2*j], acc[i][2*j+1], accp[i][j]);

    // ---- epilogue: single exp stream — q uses exp(a*SCALE), k uses exp(a) ----
    const int f32f = g_maskflags[0], u8f = g_maskflags[1];
    const float myscale = (tx < 8) ? 0.125f : 1.0f;

    bool mzv[8];
    if (tx >= 8) {
        #pragma unroll
        for (int i = 0; i < 8; ++i) {
            int grow = bh * N_ + nband * 128 + ty * 8 + i;
            if (f32f)      mzv[i] = ((const float*)mask)[grow] != 0.f;
            else if (u8f)  mzv[i] = ((const unsigned char*)mask)[grow] != 0;
            else           mzv[i] = ((const int*)mask)[grow] != 0;
        }
    }

    float ksl[8];
    #pragma unroll
    for (int j = 0; j < 8; ++j) ksl[j] = 0.f;

    #pragma unroll
    for (int i = 0; i < 8; ++i) {
        float ex[8];
        float lsum = 0.f;
        #pragma unroll
        for (int j = 0; j < 8; ++j) { ex[j] = __expf(acc[i][j] * myscale); lsum += ex[j]; }
        #pragma unroll
        for (int off = 4; off > 0; off >>= 1)
            lsum += __shfl_xor_sync(0xffffffff, lsum, off);   // k-groups reduce too (unused)
        float inv = 1.f / lsum;

        if (tx < 8) {
            #pragma unroll
            for (int j = 0; j < 8; ++j) acc[i][j] = ex[j] * inv;
        } else {
            bool mz = mzv[i];
            #pragma unroll
            for (int j = 0; j < 8; ++j) {
                ksl[j] += ex[j];                 // ksum pre-mask
                acc[i][j] = mz ? 0.f : ex[j];
            }
        }
    }

    // ---- ksum reduction (red at sm+32768, 4KB) ----
    float* red = (float*)(sm + 32768);
    __syncthreads();                 // mainloop smem free
    if (tx >= 8) {
        #pragma unroll
        for (int j = 0; j < 8; ++j) red[ty * 64 + (tx - 8) * 8 + j] = ksl[j];
    }
    __syncthreads();
    if (tid < 64) {
        float s = 0.f;
        #pragma unroll
        for (int r = 0; r < 16; ++r) s += red[r * 64 + tid];
        atomicAdd(&g_ksum[bh * 64 + tid], s);
    }

    // ---- partial ctx: two 64-row halves staged in smem ----
    float* qsm = (float*)sm;             // [64][64]
    float* ksm = (float*)(sm + 16384);   // [64][64]
    const int d0 = (tid >> 4) * 4, e0 = (tid & 15) * 4;

    u64 cacc[4][2];
    #pragma unroll
    for (int i = 0; i < 4; ++i) { cacc[i][0] = 0ull; cacc[i][1] = 0ull; }

    #pragma unroll
    for (int half = 0; half < 2; ++half) {
        __syncthreads();
        if ((ty >> 3) == half) {
            int lty = ty & 7;
            if (tx < 8) {
                #pragma unroll
                for (int i = 0; i < 8; ++i)
                    #pragma unroll
                    for (int j = 0; j < 8; ++j)
                        qsm[(lty * 8 + i) * 64 + tx * 8 + j] = acc[i][j];
            } else {
                #pragma unroll
                for (int i = 0; i < 8; ++i)
                    #pragma unroll
                    for (int j = 0; j < 8; ++j)
                        ksm[(lty * 8 + i) * 64 + (tx - 8) * 8 + j] = acc[i][j];
            }
        }
        __syncthreads();

        #pragma unroll 4
        for (int r = 0; r < 64; ++r) {
            float4 qa = *(const float4*)&qsm[r * 64 + d0];
            u64 kb0 = *(const u64*)&ksm[r * 64 + e0];
            u64 kb1 = *(const u64*)&ksm[r * 64 + e0 + 2];
            u64 p0 = pack_dup(qa.x), p1 = pack_dup(qa.y);
            u64 p2 = pack_dup(qa.z), p3 = pack_dup(qa.w);
            fma2(cacc[0][0], p0, kb0); fma2(cacc[0][1], p0, kb1);
            fma2(cacc[1][0], p1, kb0); fma2(cacc[1][1], p1, kb1);
            fma2(cacc[2][0], p2, kb0); fma2(cacc[2][1], p2, kb1);
            fma2(cacc[3][0], p3, kb0); fma2(cacc[3][1], p3, kb1);
        }
    }

    #pragma unroll
    for (int i = 0; i < 4; ++i) {
        float v0, v1, v2, v3;
        unpack2(v0, v1, cacc[i][0]);
        unpack2(v2, v3, cacc[i][1]);
        float* dst = &g_ctx[bh * 4096 + (d0 + i) * 64 + e0];
        atomicAdd(dst + 0, v0);
        atomicAdd(dst + 1, v1);
        atomicAdd(dst + 2, v2);
        atomicAdd(dst + 3, v3);
    }
}

// =============================================================================
// W3[b] += Wv_slice @ W2[b]  (K-split 2, atomicAdd). grid (4, 16, 2), 256 thr.
// (R14 configuration — measured 41 us; 512-thread variant regressed.)
// =============================================================================
__global__ __launch_bounds__(256, 2) void w3_kernel(const float* __restrict__ Wqkv) {
    __shared__ __align__(16) char sm[SMEM_TOT];
    uint32_t sb = smem_u32(sm);

    const int nBase = blockIdx.x * 128;
    const int mBase = blockIdx.y * 128;
    const int b     = mBase >> 9;
    const int kr0   = mBase & 511;
    const int ks    = blockIdx.z;                // 0..1

    u64 accp[8][4];
    gemm_mainloop(accp, sm, sb,
                  Wqkv + (size_t)kr0 * QKVN + 1024, QKVN,
                  g_w2 + (size_t)b * DIM_ * DIM_ + nBase, DIM_,
                  ks * 16, 16);

    float acc[8][8];
    #pragma unroll
    for (int i = 0; i < 8; ++i)
        #pragma unroll
        for (int j = 0; j < 4; ++j)
            unpack2(acc[i][2*j], acc[i][2*j+1], accp[i][j]);

    const int tid = threadIdx.x;
    const int ty = tid >> 4, tx = tid & 15;
    const int m0 = ty * 8, n0 = tx * 8;

    #pragma unroll
    for (int i = 0; i < 8; ++i) {
        float* dst = g_w3 + (size_t)b * DIM_ * DIM_ + (size_t)(kr0 + m0 + i) * DIM_ + nBase + n0;
        #pragma unroll
        for (int j = 0; j < 8; ++j) atomicAdd(dst + j, acc[i][j]);
    }
}

// =============================================================================
// GEMM2: out = X @ W3[b] + bout.  grid (4, 256).
// =============================================================================
__global__ __launch_bounds__(256, 2) void gemm2_cp(const float* __restrict__ X,
                                                   const float* __restrict__ bias,
                                                   float* __restrict__ out) {
    __shared__ __align__(16) char sm[SMEM_TOT];
    uint32_t sb = smem_u32(sm);

    const int nBase = blockIdx.x * 128;
    const int mBase = blockIdx.y * 128;
    const int b     = mBase >> 13;

    u64 accp[8][4];
    gemm_mainloop(accp, sm, sb,
                  X + (size_t)mBase * DIM_, DIM_,
                  g_w3 + (size_t)b * DIM_ * DIM_ + nBase, DIM_, 0, 32);

    float acc[8][8];
    #pragma unroll
    for (int i = 0; i < 8; ++i)
        #pragma unroll
        for (int j = 0; j < 4; ++j)
            unpack2(acc[i][2*j], acc[i][2*j+1], accp[i][j]);

    const int tid = threadIdx.x;
    const int ty = tid >> 4, tx = tid & 15;
    const int m0 = ty * 8, n0 = tx * 8;

    #pragma unroll
    for (int i = 0; i < 8; ++i) {
        int gm = mBase + m0 + i;
        #pragma unroll
        for (int j = 0; j < 8; j += 4) {
            int gn = nBase + n0 + j;
            float4 bv = *(const float4*)&bias[gn];
            float4 o = make_float4(acc[i][j] + bv.x, acc[i][j+1] + bv.y,
                                   acc[i][j+2] + bv.z, acc[i][j+3] + bv.w);
            *(float4*)&out[(size_t)gm * DIM_ + gn] = o;
        }
    }
}

// =============================================================================
// Mask dtype detection (bool may be serialized as u8 / i32 / f32).
// =============================================================================
__global__ __launch_bounds__(256) void detect_mask_kernel(const unsigned char* __restrict__ m) {
    int i = blockIdx.x * 256 + threadIdx.x;
    uchar4 v = ((const uchar4*)m)[i];
    bool f32sig = (v.w == 0x3f);
    bool offnz  = (v.y | v.z | v.w) != 0;
    unsigned b1 = __ballot_sync(0xffffffff, f32sig);
    unsigned b2 = __ballot_sync(0xffffffff, offnz);
    if ((threadIdx.x & 31) == 0) {
        if (b1) atomicOr(&g_maskflags[0], 1);
        if (b2) atomicOr(&g_maskflags[1], 1);
    }
}

// =============================================================================
// W2[b][h*64+d][c] = sum_e (ctxU[bh][d][e]/ksum[bh][e]) * Wout[h*64+e][c]
// grid (32 bh, 4 c-blocks of 128). Wout staged in smem (two 32-row halves).
// =============================================================================
__global__ __launch_bounds__(256) void w2_kernel(const float* __restrict__ Wout) {
    int bh = blockIdx.x, cb = blockIdx.y;
    int b = bh >> 3, h = bh & 7;
    __shared__ float cs[64][64];
    __shared__ float ws[32][128];
    int t = threadIdx.x;

    float4 kv = *(const float4*)&g_ksum[bh * 64 + (t & 15) * 4];
    const float4* cp4 = (const float4*)(g_ctx + bh * 4096);
    #pragma unroll
    for (int u = 0; u < 4; ++u) {
        float4 c4 = cp4[u * 256 + t];
        c4.x /= kv.x; c4.y /= kv.y; c4.z /= kv.z; c4.w /= kv.w;
        ((float4*)cs)[u * 256 + t] = c4;
    }

    int ty = t >> 4, tx = t & 15;
    int c0 = cb * 128 + tx * 8;
    const float* wbase = Wout + (size_t)(h * 64) * DIM_ + cb * 128;

    float acc[4][8];
    #pragma unroll
    for (int i = 0; i < 4; ++i)
        #pragma unroll
        for (int j = 0; j < 8; ++j) acc[i][j] = 0.f;

    #pragma unroll
    for (int half = 0; half < 2; ++half) {
        if (half) __syncthreads();
        #pragma unroll
        for (int u = 0; u < 4; ++u) {
            int idx = u * 256 + t;
            int e = idx >> 5, c4 = idx & 31;
            *(float4*)&ws[e][c4 * 4] =
                *(const float4*)&wbase[(size_t)(half * 32 + e) * DIM_ + c4 * 4];
        }
        __syncthreads();

        #pragma unroll 4
        for (int e = 0; e < 32; ++e) {
            float4 w0 = *(const float4*)&ws[e][tx * 8];
            float4 w1 = *(const float4*)&ws[e][tx * 8 + 4];
            float wv[8] = {w0.x, w0.y, w0.z, w0.w, w1.x, w1.y, w1.z, w1.w};
            #pragma unroll
            for (int i = 0; i < 4; ++i) {
                float cv = cs[ty * 4 + i][half * 32 + e];
                #pragma unroll
                for (int j = 0; j < 8; ++j) acc[i][j] += cv * wv[j];
            }
        }
    }

    #pragma unroll
    for (int i = 0; i < 4; ++i) {
        size_t row = (size_t)b * DIM_ + h * 64 + ty * 4 + i;
        float* dst = g_w2 + row * DIM_ + c0;
        *(float4*)(dst)     = make_float4(acc[i][0], acc[i][1], acc[i][2], acc[i][3]);
        *(float4*)(dst + 4) = make_float4(acc[i][4], acc[i][5], acc[i][6], acc[i][7]);
    }
}

// =============================================================================
extern "C" void kernel_launch(void* const* d_in, const int* in_sizes, int n_in,
                              void* d_out, int out_size) {
    const float* x    = (const float*)d_in[0];
    const void*  mask = d_in[1];
    const float* Wqkv = (const float*)d_in[2];
    const float* Wout = (const float*)d_in[3];
    const float* bout = (const float*)d_in[4];
    float* out = (float*)d_out;

    void *pks, *pctx, *pfl, *pw3;
    cudaGetSymbolAddress(&pks,  g_ksum);
    cudaGetSymbolAddress(&pctx, g_ctx);
    cudaGetSymbolAddress(&pfl,  g_maskflags);
    cudaGetSymbolAddress(&pw3,  g_w3);
    cudaMemsetAsync(pks,  0, sizeof(float) * BH_ * DH_);
    cudaMemsetAsync(pctx, 0, sizeof(float) * BH_ * DH_ * DH_);
    cudaMemsetAsync(pfl,  0, 2 * sizeof(int));
    cudaMemsetAsync(pw3,  0, sizeof(float) * B_ * DIM_ * DIM_);

    detect_mask_kernel<<<(BH_ * N_) / 1024, 256>>>((const unsigned char*)mask);

    gemm1_fused<<<dim3(BH_, N_ / 128), 256>>>(x, Wqkv, mask);   // q,k + ctx + ksum

    w2_kernel<<<dim3(BH_, 4), 256>>>(Wout);
    w3_kernel<<<dim3(4, 16, 2), 256>>>(Wqkv);

    gemm2_cp<<<dim3(DIM_ / 128, MROWS / 128), 256>>>(x, bout, out);
}

// round 17
// speedup vs baseline: 1.0185x; 1.0018x over previous
#include <cuda_runtime.h>
#include <math.h>
#include <stdint.h>

#define B_   4
#define N_   8192
#define DIM_ 512
#define H_   8
#define DH_  64
#define BH_  (B_*H_)          // 32
#define MROWS (B_*N_)         // 32768
#define QKVN  (3*DIM_)        // 1536

typedef unsigned long long u64;

// ---------------- scratch (device globals; no allocs allowed) ----------------
__device__ float g_ctx[BH_*DH_*DH_];   // [bh][d][e]  UNNORMALIZED (divide in w2)
__device__ float g_w2[(size_t)B_*DIM_*DIM_];   // [b][h*64+d][c] = (ctx_h/ksum) @ Wout_h
__device__ float g_w3[(size_t)B_*DIM_*DIM_];   // [b][k][c]      = Wv @ W2[b]
__device__ float g_ksum[BH_*DH_];      // [bh][e] = sum_n exp(k)
__device__ int   g_maskflags[2];

// ---------------- helpers ----------------
__device__ __forceinline__ uint32_t smem_u32(const void* p) {
    uint32_t a;
    asm("{ .reg .u64 t; cvta.to.shared.u64 t, %1; cvt.u32.u64 %0, t; }" : "=r"(a) : "l"(p));
    return a;
}
__device__ __forceinline__ void cp16(uint32_t dst, const void* src) {
    asm volatile("cp.async.ca.shared.global [%0], [%1], 16;" :: "r"(dst), "l"(src));
}
__device__ __forceinline__ void cp_commit() {
    asm volatile("cp.async.commit_group;" ::: "memory");
}
template<int N> __device__ __forceinline__ void cp_wait() {
    asm volatile("cp.async.wait_group %0;" :: "n"(N) : "memory");
}

// packed f32x2 helpers (FFMA2)
__device__ __forceinline__ u64 pack_dup(float a) {
    u64 p;
    asm("mov.b64 %0, {%1, %1};" : "=l"(p) : "f"(a));
    return p;
}
__device__ __forceinline__ void fma2(u64& d, u64 a, u64 b) {
    asm("fma.rn.f32x2 %0, %1, %2, %0;" : "+l"(d) : "l"(a), "l"(b));
}
__device__ __forceinline__ void unpack2(float& lo, float& hi, u64 p) {
    asm("mov.b64 {%0, %1}, %2;" : "=f"(lo), "=f"(hi) : "l"(p));
}
__device__ __forceinline__ void lds_v2u64(u64& a, u64& b, uint32_t addr) {
    asm volatile("ld.shared.v2.u64 {%0, %1}, [%2];" : "=l"(a), "=l"(b) : "r"(addr));
}

// smem geometry: A stage = 128 rows x (16 floats + 4 pad) = 10240 B
//                B stage = 16 rows x (128 floats + 4 pad) = 8448 B
#define A_STAGE 10240
#define B_BASE  20480
#define B_STAGE 8448
#define SMEM_TOT 37376

// =============================================================================
// Shared cp.async double-buffered f32x2 mainloop (generic B stride), 256 thr.
// =============================================================================
__device__ __forceinline__ void gemm_mainloop(u64 (&accp)[8][4], char* sm, uint32_t sb,
                                              const float* __restrict__ Ag, int AW,
                                              const float* __restrict__ Bg, int BW,
                                              int ch0, int nch) {
    const int tid = threadIdx.x;
    const int ty = tid >> 4, tx = tid & 15;
    const int m0 = ty * 8;

    #pragma unroll
    for (int i = 0; i < 8; ++i)
        #pragma unroll
        for (int j = 0; j < 4; ++j) accp[i][j] = 0ull;

    const int ar_ = tid >> 2,  ac_ = tid & 3;
    const int br_ = tid >> 5,  bc_ = tid & 31;

    auto issue = [&](int ch, int p) {
        uint32_t Ab = sb + p * A_STAGE;
        uint32_t Bb = sb + B_BASE + p * B_STAGE;
        int kc = (ch0 + ch) * 16;
        #pragma unroll
        for (int i = 0; i < 2; ++i) {
            int r = ar_ + i * 64;
            cp16(Ab + r * 80 + ac_ * 16, Ag + (size_t)r * AW + kc + ac_ * 4);
        }
        #pragma unroll
        for (int i = 0; i < 2; ++i) {
            int r = br_ + i * 8;
            cp16(Bb + r * 528 + bc_ * 16, Bg + (size_t)(kc + r) * BW + bc_ * 4);
        }
    };

    issue(0, 0);
    cp_commit();

    #pragma unroll 1
    for (int ch = 0; ch < nch; ++ch) {
        int p = ch & 1;
        cp_wait<0>();
        __syncthreads();
        if (ch < nch - 1) { issue(ch + 1, p ^ 1); cp_commit(); }

        const float* As = (const float*)(sm + p * A_STAGE);
        const char*  Bs = sm + B_BASE + p * B_STAGE;

        #pragma unroll
        for (int kk = 0; kk < 16; ++kk) {
            const char* brow = Bs + kk * 528 + tx * 32;
            u64 b0 = *(const u64*)(brow);
            u64 b1 = *(const u64*)(brow + 8);
            u64 b2 = *(const u64*)(brow + 16);
            u64 b3 = *(const u64*)(brow + 24);
            #pragma unroll
            for (int i = 0; i < 8; ++i) {
                u64 pa = pack_dup(As[(m0 + i) * 20 + kk]);
                fma2(accp[i][0], pa, b0);
                fma2(accp[i][1], pa, b1);
                fma2(accp[i][2], pa, b2);
                fma2(accp[i][3], pa, b3);
            }
        }
    }
}

// =============================================================================
// GEMM1 FUSED: per (b,h) CTA computes [q_h | k_h] = X_band @ W_gather, then
// q-softmax / k exp+mask / ksum / partial ctx — no q/k gmem round trip.
// grid (32 bh, 64 nbands of 128 rows).
// =============================================================================
__global__ __launch_bounds__(256, 2) void gemm1_fused(const float* __restrict__ X,
                                                      const float* __restrict__ W,
                                                      const void* __restrict__ mask) {
    __shared__ __align__(16) char sm[SMEM_TOT];
    uint32_t sb = smem_u32(sm);

    const int bh = blockIdx.x, nband = blockIdx.y;
    const int b = bh >> 3, h = bh & 7;
    const float* Ag = X + ((size_t)b * N_ + nband * 128) * DIM_;

    const int tid = threadIdx.x;
    const int ty = tid >> 4, tx = tid & 15;
    const int m0 = ty * 8;

    u64 accp[8][4];
    #pragma unroll
    for (int i = 0; i < 8; ++i)
        #pragma unroll
        for (int j = 0; j < 4; ++j) accp[i][j] = 0ull;

    const int ar_ = tid >> 2,  ac_ = tid & 3;
    const int br_ = tid >> 5,  bc_ = tid & 31;
    const int bcol = (bc_ < 16) ? (h * 64 + bc_ * 4)
                                : (512 + h * 64 + (bc_ - 16) * 4);

    auto issue = [&](int ch, int p) {
        uint32_t Ab = sb + p * A_STAGE;
        uint32_t Bb = sb + B_BASE + p * B_STAGE;
        int kc = ch * 16;
        #pragma unroll
        for (int i = 0; i < 2; ++i) {
            int r = ar_ + i * 64;
            cp16(Ab + r * 80 + ac_ * 16, Ag + (size_t)r * DIM_ + kc + ac_ * 4);
        }
        #pragma unroll
        for (int i = 0; i < 2; ++i) {
            int r = br_ + i * 8;
            cp16(Bb + r * 528 + bc_ * 16, W + (size_t)(kc + r) * QKVN + bcol);
        }
    };

    issue(0, 0);
    cp_commit();

    #pragma unroll 1
    for (int ch = 0; ch < 32; ++ch) {
        int p = ch & 1;
        cp_wait<0>();
        __syncthreads();
        if (ch < 31) { issue(ch + 1, p ^ 1); cp_commit(); }

        const float* As = (const float*)(sm + p * A_STAGE);
        const char*  Bs = sm + B_BASE + p * B_STAGE;

        #pragma unroll
        for (int kk = 0; kk < 16; ++kk) {
            const char* brow = Bs + kk * 528 + tx * 32;
            u64 b0 = *(const u64*)(brow);
            u64 b1 = *(const u64*)(brow + 8);
            u64 b2 = *(const u64*)(brow + 16);
            u64 b3 = *(const u64*)(brow + 24);
            #pragma unroll
            for (int i = 0; i < 8; ++i) {
                u64 pa = pack_dup(As[(m0 + i) * 20 + kk]);
                fma2(accp[i][0], pa, b0);
                fma2(accp[i][1], pa, b1);
                fma2(accp[i][2], pa, b2);
                fma2(accp[i][3], pa, b3);
            }
        }
    }

    float acc[8][8];
    #pragma unroll
    for (int i = 0; i < 8; ++i)
        #pragma unroll
        for (int j = 0; j < 4; ++j)
            unpack2(acc[i][2*j], acc[i][2*j+1], accp[i][j]);

    // ---- epilogue: single exp stream — q uses exp(a*SCALE), k uses exp(a) ----
    const int f32f = g_maskflags[0], u8f = g_maskflags[1];
    const bool isq = (tx < 8);
    const float myscale = isq ? 0.125f : 1.0f;

    bool mzv[8];
    if (!isq) {
        #pragma unroll
        for (int i = 0; i < 8; ++i) {
            int grow = bh * N_ + nband * 128 + ty * 8 + i;
            if (f32f)      mzv[i] = ((const float*)mask)[grow] != 0.f;
            else if (u8f)  mzv[i] = ((const unsigned char*)mask)[grow] != 0;
            else           mzv[i] = ((const int*)mask)[grow] != 0;
        }
    }

    float ksl[8];
    #pragma unroll
    for (int j = 0; j < 8; ++j) ksl[j] = 0.f;

    #pragma unroll
    for (int i = 0; i < 8; ++i) {
        float ex[8];
        #pragma unroll
        for (int j = 0; j < 8; ++j) ex[j] = __expf(acc[i][j] * myscale);

        if (isq) {
            // q-lanes in each warp are exactly lanes 0-7 and 16-23 -> mask 0x00FF00FF;
            // butterfly offs 4/2/1 stay within each 8-lane group.
            float lsum = ex[0] + ex[1] + ex[2] + ex[3] + ex[4] + ex[5] + ex[6] + ex[7];
            #pragma unroll
            for (int off = 4; off > 0; off >>= 1)
                lsum += __shfl_xor_sync(0x00FF00FFu, lsum, off);
            float inv = 1.f / lsum;
            #pragma unroll
            for (int j = 0; j < 8; ++j) acc[i][j] = ex[j] * inv;
        } else {
            bool mz = mzv[i];
            #pragma unroll
            for (int j = 0; j < 8; ++j) {
                ksl[j] += ex[j];                 // ksum pre-mask
                acc[i][j] = mz ? 0.f : ex[j];
            }
        }
    }

    // ---- ksum reduction (red at sm+32768, 4KB) ----
    float* red = (float*)(sm + 32768);
    __syncthreads();                 // mainloop smem free
    if (!isq) {
        #pragma unroll
        for (int j = 0; j < 8; ++j) red[ty * 64 + (tx - 8) * 8 + j] = ksl[j];
    }
    __syncthreads();
    if (tid < 64) {
        float s = 0.f;
        #pragma unroll
        for (int r = 0; r < 16; ++r) s += red[r * 64 + tid];
        atomicAdd(&g_ksum[bh * 64 + tid], s);
    }

    // ---- partial ctx: two 64-row halves staged in smem ----
    float* qsm = (float*)sm;             // [64][64]
    float* ksm = (float*)(sm + 16384);   // [64][64]
    const uint32_t ksb = sb + 16384;
    const int d0 = (tid >> 4) * 4, e0 = (tid & 15) * 4;

    u64 cacc[4][2];
    #pragma unroll
    for (int i = 0; i < 4; ++i) { cacc[i][0] = 0ull; cacc[i][1] = 0ull; }

    #pragma unroll
    for (int half = 0; half < 2; ++half) {
        __syncthreads();
        if ((ty >> 3) == half) {
            int lty = ty & 7;
            if (isq) {
                #pragma unroll
                for (int i = 0; i < 8; ++i)
                    #pragma unroll
                    for (int j = 0; j < 8; ++j)
                        qsm[(lty * 8 + i) * 64 + tx * 8 + j] = acc[i][j];
            } else {
                #pragma unroll
                for (int i = 0; i < 8; ++i)
                    #pragma unroll
                    for (int j = 0; j < 8; ++j)
                        ksm[(lty * 8 + i) * 64 + (tx - 8) * 8 + j] = acc[i][j];
            }
        }
        __syncthreads();

        #pragma unroll 4
        for (int r = 0; r < 64; ++r) {
            float4 qa = *(const float4*)&qsm[r * 64 + d0];
            u64 kb0, kb1;
            lds_v2u64(kb0, kb1, ksb + (uint32_t)((r * 64 + e0) * 4));
            u64 p0 = pack_dup(qa.x), p1 = pack_dup(qa.y);
            u64 p2 = pack_dup(qa.z), p3 = pack_dup(qa.w);
            fma2(cacc[0][0], p0, kb0); fma2(cacc[0][1], p0, kb1);
            fma2(cacc[1][0], p1, kb0); fma2(cacc[1][1], p1, kb1);
            fma2(cacc[2][0], p2, kb0); fma2(cacc[2][1], p2, kb1);
            fma2(cacc[3][0], p3, kb0); fma2(cacc[3][1], p3, kb1);
        }
    }

    #pragma unroll
    for (int i = 0; i < 4; ++i) {
        float v0, v1, v2, v3;
        unpack2(v0, v1, cacc[i][0]);
        unpack2(v2, v3, cacc[i][1]);
        float* dst = &g_ctx[bh * 4096 + (d0 + i) * 64 + e0];
        atomicAdd(dst + 0, v0);
        atomicAdd(dst + 1, v1);
        atomicAdd(dst + 2, v2);
        atomicAdd(dst + 3, v3);
    }
}

// =============================================================================
// W3[b] += Wv_slice @ W2[b]  (K-split 2, atomicAdd). grid (4, 16, 2), 256 thr.
// =============================================================================
__global__ __launch_bounds__(256, 2) void w3_kernel(const float* __restrict__ Wqkv) {
    __shared__ __align__(16) char sm[SMEM_TOT];
    uint32_t sb = smem_u32(sm);

    const int nBase = blockIdx.x * 128;
    const int mBase = blockIdx.y * 128;
    const int b     = mBase >> 9;
    const int kr0   = mBase & 511;
    const int ks    = blockIdx.z;                // 0..1

    u64 accp[8][4];
    gemm_mainloop(accp, sm, sb,
                  Wqkv + (size_t)kr0 * QKVN + 1024, QKVN,
                  g_w2 + (size_t)b * DIM_ * DIM_ + nBase, DIM_,
                  ks * 16, 16);

    float acc[8][8];
    #pragma unroll
    for (int i = 0; i < 8; ++i)
        #pragma unroll
        for (int j = 0; j < 4; ++j)
            unpack2(acc[i][2*j], acc[i][2*j+1], accp[i][j]);

    const int tid = threadIdx.x;
    const int ty = tid >> 4, tx = tid & 15;
    const int m0 = ty * 8, n0 = tx * 8;

    #pragma unroll
    for (int i = 0; i < 8; ++i) {
        float* dst = g_w3 + (size_t)b * DIM_ * DIM_ + (size_t)(kr0 + m0 + i) * DIM_ + nBase + n0;
        #pragma unroll
        for (int j = 0; j < 8; ++j) atomicAdd(dst + j, acc[i][j]);
    }
}

// =============================================================================
// GEMM2: out = X @ W3[b] + bout.  grid (4, 256).
// =============================================================================
__global__ __launch_bounds__(256, 2) void gemm2_cp(const float* __restrict__ X,
                                                   const float* __restrict__ bias,
                                                   float* __restrict__ out) {
    __shared__ __align__(16) char sm[SMEM_TOT];
    uint32_t sb = smem_u32(sm);

    const int nBase = blockIdx.x * 128;
    const int mBase = blockIdx.y * 128;
    const int b     = mBase >> 13;

    u64 accp[8][4];
    gemm_mainloop(accp, sm, sb,
                  X + (size_t)mBase * DIM_, DIM_,
                  g_w3 + (size_t)b * DIM_ * DIM_ + nBase, DIM_, 0, 32);

    float acc[8][8];
    #pragma unroll
    for (int i = 0; i < 8; ++i)
        #pragma unroll
        for (int j = 0; j < 4; ++j)
            unpack2(acc[i][2*j], acc[i][2*j+1], accp[i][j]);

    const int tid = threadIdx.x;
    const int ty = tid >> 4, tx = tid & 15;
    const int m0 = ty * 8, n0 = tx * 8;

    #pragma unroll
    for (int i = 0; i < 8; ++i) {
        int gm = mBase + m0 + i;
        #pragma unroll
        for (int j = 0; j < 8; j += 4) {
            int gn = nBase + n0 + j;
            float4 bv = *(const float4*)&bias[gn];
            float4 o = make_float4(acc[i][j] + bv.x, acc[i][j+1] + bv.y,
                                   acc[i][j+2] + bv.z, acc[i][j+3] + bv.w);
            *(float4*)&out[(size_t)gm * DIM_ + gn] = o;
        }
    }
}

// =============================================================================
// Mask dtype detection (bool may be serialized as u8 / i32 / f32).
// =============================================================================
__global__ __launch_bounds__(256) void detect_mask_kernel(const unsigned char* __restrict__ m) {
    int i = blockIdx.x * 256 + threadIdx.x;
    uchar4 v = ((const uchar4*)m)[i];
    bool f32sig = (v.w == 0x3f);
    bool offnz  = (v.y | v.z | v.w) != 0;
    unsigned b1 = __ballot_sync(0xffffffff, f32sig);
    unsigned b2 = __ballot_sync(0xffffffff, offnz);
    if ((threadIdx.x & 31) == 0) {
        if (b1) atomicOr(&g_maskflags[0], 1);
        if (b2) atomicOr(&g_maskflags[1], 1);
    }
}

// =============================================================================
// W2[b][h*64+d][c] = sum_e (ctxU[bh][d][e]/ksum[bh][e]) * Wout[h*64+e][c]
// grid (32 bh, 4 c-blocks of 128). Wout staged in smem (two 32-row halves).
// =============================================================================
__global__ __launch_bounds__(256) void w2_kernel(const float* __restrict__ Wout) {
    int bh = blockIdx.x, cb = blockIdx.y;
    int b = bh >> 3, h = bh & 7;
    __shared__ float cs[64][64];
    __shared__ float ws[32][128];
    int t = threadIdx.x;

    float4 kv = *(const float4*)&g_ksum[bh * 64 + (t & 15) * 4];
    const float4* cp4 = (const float4*)(g_ctx + bh * 4096);
    #pragma unroll
    for (int u = 0; u < 4; ++u) {
        float4 c4 = cp4[u * 256 + t];
        c4.x /= kv.x; c4.y /= kv.y; c4.z /= kv.z; c4.w /= kv.w;
        ((float4*)cs)[u * 256 + t] = c4;
    }

    int ty = t >> 4, tx = t & 15;
    int c0 = cb * 128 + tx * 8;
    const float* wbase = Wout + (size_t)(h * 64) * DIM_ + cb * 128;

    float acc[4][8];
    #pragma unroll
    for (int i = 0; i < 4; ++i)
        #pragma unroll
        for (int j = 0; j < 8; ++j) acc[i][j] = 0.f;

    #pragma unroll
    for (int half = 0; half < 2; ++half) {
        if (half) __syncthreads();
        #pragma unroll
        for (int u = 0; u < 4; ++u) {
            int idx = u * 256 + t;
            int e = idx >> 5, c4 = idx & 31;
            *(float4*)&ws[e][c4 * 4] =
                *(const float4*)&wbase[(size_t)(half * 32 + e) * DIM_ + c4 * 4];
        }
        __syncthreads();

        #pragma unroll 4
        for (int e = 0; e < 32; ++e) {
            float4 w0 = *(const float4*)&ws[e][tx * 8];
            float4 w1 = *(const float4*)&ws[e][tx * 8 + 4];
            float wv[8] = {w0.x, w0.y, w0.z, w0.w, w1.x, w1.y, w1.z, w1.w};
            #pragma unroll
            for (int i = 0; i < 4; ++i) {
                float cv = cs[ty * 4 + i][half * 32 + e];
                #pragma unroll
                for (int j = 0; j < 8; ++j) acc[i][j] += cv * wv[j];
            }
        }
    }

    #pragma unroll
    for (int i = 0; i < 4; ++i) {
        size_t row = (size_t)b * DIM_ + h * 64 + ty * 4 + i;
        float* dst = g_w2 + row * DIM_ + c0;
        *(float4*)(dst)     = make_float4(acc[i][0], acc[i][1], acc[i][2], acc[i][3]);
        *(float4*)(dst + 4) = make_float4(acc[i][4], acc[i][5], acc[i][6], acc[i][7]);
    }
}

// =============================================================================
extern "C" void kernel_launch(void* const* d_in, const int* in_sizes, int n_in,
                              void* d_out, int out_size) {
    const float* x    = (const float*)d_in[0];
    const void*  mask = d_in[1];
    const float* Wqkv = (const float*)d_in[2];
    const float* Wout = (const float*)d_in[3];
    const float* bout = (const float*)d_in[4];
    float* out = (float*)d_out;

    void *pks, *pctx, *pfl, *pw3;
    cudaGetSymbolAddress(&pks,  g_ksum);
    cudaGetSymbolAddress(&pctx, g_ctx);
    cudaGetSymbolAddress(&pfl,  g_maskflags);
    cudaGetSymbolAddress(&pw3,  g_w3);
    cudaMemsetAsync(pks,  0, sizeof(float) * BH_ * DH_);
    cudaMemsetAsync(pctx, 0, sizeof(float) * BH_ * DH_ * DH_);
    cudaMemsetAsync(pfl,  0, 2 * sizeof(int));
    cudaMemsetAsync(pw3,  0, sizeof(float) * B_ * DIM_ * DIM_);

    detect_mask_kernel<<<(BH_ * N_) / 1024, 256>>>((const unsigned char*)mask);

    gemm1_fused<<<dim3(BH_, N_ / 128), 256>>>(x, Wqkv, mask);   // q,k + ctx + ksum

    w2_kernel<<<dim3(BH_, 4), 256>>>(Wout);
    w3_kernel<<<dim3(4, 16, 2), 256>>>(Wqkv);

    gemm2_cp<<<dim3(DIM_ / 128, MROWS / 128), 256>>>(x, bout, out);
}